// round 1
// baseline (speedup 1.0000x reference)
#include <cuda_runtime.h>
#include <cstdint>

// Problem constants (fixed shapes)
#define BB   2
#define NN   32768
#define KK   16
#define PP   (BB * NN)        // 65536 points
#define CH   64
#define COLSZ ((size_t)CH * NN)   // elements per (64,N) slab per batch

// ---------------- scratch (static __device__ allocations; no runtime alloc) ----
__device__ float g_WcT  [64  * 64];   // w_corr^T   [k][c]
__device__ float g_WmeT [128 * 64];   // w_me^T     [k][c] (c padded 61->64 with 0)
__device__ float g_WzT  [192 * 64];
__device__ float g_WrT  [192 * 64];
__device__ float g_WqT  [192 * 64];
__device__ float g_Wfh1T[64  * 64];
__device__ float g_Wsc1T[67  * 64];   // rows 0..63 = feat part, 64..66 = edge_feat part
__device__ float g_Wsc2T[64  * 64];
__device__ float g_Wsc3T[64  * 64];
__device__ float g_Wo1T [128 * 64];   // w_out1^T (cols 0..63 = sc, 64..127 = o1)

__device__ float g_motion[BB * CH * NN];  // (B,64,N) channel-major
__device__ float g_z     [BB * CH * NN];
__device__ float g_r     [BB * CH * NN];
__device__ float g_nnT   [(size_t)PP * CH]; // net_new transposed (B,N,64) point-major
__device__ float g_sc    [BB * CH * NN];

// ---------------- helpers ----------------------------------------------------
__device__ __forceinline__ void fma_row(float (&acc)[64], const float* Wrow, float h) {
    const float4* w4 = reinterpret_cast<const float4*>(Wrow);
#pragma unroll
    for (int i = 0; i < 16; i++) {
        float4 w = __ldg(w4 + i);
        acc[4*i + 0] += w.x * h;
        acc[4*i + 1] += w.y * h;
        acc[4*i + 2] += w.z * h;
        acc[4*i + 3] += w.w * h;
    }
}

__device__ __forceinline__ float sigmf(float x) { return 1.0f / (1.0f + __expf(-x)); }

// ---------------- kernel 0: weight transpose ---------------------------------
__global__ void k_prep(const float* __restrict__ wc,  const float* __restrict__ wme,
                       const float* __restrict__ wz,  const float* __restrict__ wr,
                       const float* __restrict__ wq,  const float* __restrict__ wfh1,
                       const float* __restrict__ wsc1,const float* __restrict__ wsc2,
                       const float* __restrict__ wsc3,const float* __restrict__ wo1) {
    int stride = gridDim.x * blockDim.x;
    int t0 = blockIdx.x * blockDim.x + threadIdx.x;
    for (int t = t0; t < 64*64; t += stride) { int k = t >> 6, c = t & 63;
        g_WcT[t]   = wc  [c*64  + k];
        g_Wfh1T[t] = wfh1[c*64  + k];
        g_Wsc2T[t] = wsc2[c*64  + k];
        g_Wsc3T[t] = wsc3[c*64  + k];
    }
    for (int t = t0; t < 128*64; t += stride) { int k = t >> 6, c = t & 63;
        g_WmeT[t] = (c < 61) ? wme[c*128 + k] : 0.0f;
        g_Wo1T[t] = wo1[c*128 + k];
    }
    for (int t = t0; t < 192*64; t += stride) { int k = t >> 6, c = t & 63;
        g_WzT[t] = wz[c*192 + k];
        g_WrT[t] = wr[c*192 + k];
        g_WqT[t] = wq[c*192 + k];
    }
    for (int t = t0; t < 67*64; t += stride) { int k = t >> 6, c = t & 63;
        g_Wsc1T[t] = wsc1[c*67 + k];
    }
}

// ---------------- kernel 1: MotionEncoder ------------------------------------
// cor = relu(Wcorr@corr+b); flo = relu(Wflow@flow+b);
// mf = relu(Wme@[cor;flo]+b); motion = [mf(61); flow(3)] -> g_motion (B,64,N)
__global__ void __launch_bounds__(128) k_motion(
    const float* __restrict__ corr, const float* __restrict__ flow,
    const float* __restrict__ bcorr, const float* __restrict__ bme,
    const float* __restrict__ wflow, const float* __restrict__ bflow) {
    __shared__ float sm[64 * 128];
    int tid = threadIdx.x;
    int p = blockIdx.x * 128 + tid;
    int b = p >> 15, n = p & (NN - 1);
    size_t base = (size_t)b * COLSZ + n;

    float f0 = __ldg(flow + (size_t)p*3 + 0);
    float f1 = __ldg(flow + (size_t)p*3 + 1);
    float f2 = __ldg(flow + (size_t)p*3 + 2);

    float acc[64];
#pragma unroll
    for (int c = 0; c < 64; c++) acc[c] = __ldg(bcorr + c);
    for (int k = 0; k < 64; k++) {
        float h = __ldg(corr + base + (size_t)k * NN);
        fma_row(acc, g_WcT + k*64, h);
    }
#pragma unroll
    for (int c = 0; c < 64; c++) sm[c*128 + tid] = fmaxf(acc[c], 0.0f);  // cor

#pragma unroll
    for (int c = 0; c < 64; c++) acc[c] = (c < 61) ? __ldg(bme + c) : 0.0f;
    for (int k = 0; k < 64; k++) {                 // cor part
        float h = sm[k*128 + tid];
        fma_row(acc, g_WmeT + k*64, h);
    }
    for (int j = 0; j < 64; j++) {                 // flo part (computed on the fly)
        float h = fmaxf(__ldg(wflow + j*3 + 0) * f0 +
                        __ldg(wflow + j*3 + 1) * f1 +
                        __ldg(wflow + j*3 + 2) * f2 + __ldg(bflow + j), 0.0f);
        fma_row(acc, g_WmeT + (64 + j)*64, h);
    }
    float* mo = g_motion + base;
#pragma unroll
    for (int c = 0; c < 61; c++) mo[(size_t)c * NN] = fmaxf(acc[c], 0.0f);
    mo[(size_t)61 * NN] = f0;
    mo[(size_t)62 * NN] = f1;
    mo[(size_t)63 * NN] = f2;
}

// ---------------- kernel 2: GRU gates z, r -----------------------------------
__global__ void __launch_bounds__(128) k_zr(
    const float* __restrict__ net, const float* __restrict__ inp,
    const float* __restrict__ bz, const float* __restrict__ br) {
    int p = blockIdx.x * 128 + threadIdx.x;
    int b = p >> 15, n = p & (NN - 1);
    size_t base = (size_t)b * COLSZ + n;

    float z[64], r[64];
#pragma unroll
    for (int c = 0; c < 64; c++) { z[c] = __ldg(bz + c); r[c] = __ldg(br + c); }
    for (int k = 0; k < 64; k++) {
        float h = __ldg(net + base + (size_t)k * NN);
        fma_row(z, g_WzT + k*64, h);
        fma_row(r, g_WrT + k*64, h);
    }
    for (int k = 0; k < 64; k++) {
        float h = __ldg(inp + base + (size_t)k * NN);
        fma_row(z, g_WzT + (64 + k)*64, h);
        fma_row(r, g_WrT + (64 + k)*64, h);
    }
    for (int k = 0; k < 64; k++) {
        float h = g_motion[base + (size_t)k * NN];
        fma_row(z, g_WzT + (128 + k)*64, h);
        fma_row(r, g_WrT + (128 + k)*64, h);
    }
#pragma unroll
    for (int c = 0; c < 64; c++) {
        g_z[base + (size_t)c * NN] = sigmf(z[c]);
        g_r[base + (size_t)c * NN] = sigmf(r[c]);
    }
}

// ---------------- kernel 3: q + GRU combine ----------------------------------
// net_new -> d_out (B,64,N) and g_nnT (B,N,64)
__global__ void __launch_bounds__(128) k_q(
    const float* __restrict__ net, const float* __restrict__ inp,
    const float* __restrict__ bq, float* __restrict__ out) {
    int p = blockIdx.x * 128 + threadIdx.x;
    int b = p >> 15, n = p & (NN - 1);
    size_t base = (size_t)b * COLSZ + n;

    float q[64];
#pragma unroll
    for (int c = 0; c < 64; c++) q[c] = __ldg(bq + c);
    for (int k = 0; k < 64; k++) {
        float nv = __ldg(net + base + (size_t)k * NN);
        float rv = g_r[base + (size_t)k * NN];
        fma_row(q, g_WqT + k*64, rv * nv);
    }
    for (int k = 0; k < 64; k++) {
        float h = __ldg(inp + base + (size_t)k * NN);
        fma_row(q, g_WqT + (64 + k)*64, h);
    }
    for (int k = 0; k < 64; k++) {
        float h = g_motion[base + (size_t)k * NN];
        fma_row(q, g_WqT + (128 + k)*64, h);
    }
    float nn[64];
#pragma unroll
    for (int c = 0; c < 64; c++) {
        float nv = __ldg(net + base + (size_t)c * NN);
        float zv = g_z[base + (size_t)c * NN];
        float qv = tanhf(q[c]);
        float v = (1.0f - zv) * nv + zv * qv;
        nn[c] = v;
        out[base + (size_t)c * NN] = v;              // output #1: net_new (B,64,N)
    }
    float4* dst = reinterpret_cast<float4*>(g_nnT + (size_t)p * 64);
#pragma unroll
    for (int i = 0; i < 16; i++)
        dst[i] = make_float4(nn[4*i], nn[4*i+1], nn[4*i+2], nn[4*i+3]);
}

// ---------------- kernel 4: SetConv (gather + 3 MLP layers) -------------------
__global__ void __launch_bounds__(128) k_setconv(
    const int* __restrict__ edges, const float* __restrict__ efeat,
    const float* __restrict__ bsc1, const float* __restrict__ bsc2,
    const float* __restrict__ bsc3) {
    __shared__ float sm[64 * 128];
    int tid = threadIdx.x;
    int p = blockIdx.x * 128 + tid;
    int b = p >> 15, n = p & (NN - 1);
    size_t base = (size_t)b * COLSZ + n;

    const int*   eg = edges + (size_t)p * KK;
    const float* ef = efeat + (size_t)p * KK * 3;

    float smax[64];
#pragma unroll
    for (int c = 0; c < 64; c++) smax[c] = 0.0f;   // == max over relu values (all >= 0)

    for (int k = 0; k < KK; k++) {
        int e = __ldg(eg + k);
        const float4* nb = reinterpret_cast<const float4*>(
            g_nnT + (((size_t)b << 15) + (size_t)e) * 64);
        float e0 = __ldg(ef + k*3 + 0);
        float e1 = __ldg(ef + k*3 + 1);
        float e2 = __ldg(ef + k*3 + 2);
        float s1[64];
#pragma unroll
        for (int c = 0; c < 64; c++) s1[c] = __ldg(bsc1 + c);
        fma_row(s1, g_Wsc1T + 64*64, e0);
        fma_row(s1, g_Wsc1T + 65*64, e1);
        fma_row(s1, g_Wsc1T + 66*64, e2);
        for (int c4 = 0; c4 < 16; c4++) {
            float4 v = __ldg(nb + c4);
            fma_row(s1, g_Wsc1T + (c4*4 + 0)*64, v.x);
            fma_row(s1, g_Wsc1T + (c4*4 + 1)*64, v.y);
            fma_row(s1, g_Wsc1T + (c4*4 + 2)*64, v.z);
            fma_row(s1, g_Wsc1T + (c4*4 + 3)*64, v.w);
        }
#pragma unroll
        for (int c = 0; c < 64; c++) smax[c] = fmaxf(smax[c], s1[c]);
    }
#pragma unroll
    for (int c = 0; c < 64; c++) sm[c*128 + tid] = smax[c];

    float s2[64];
#pragma unroll
    for (int c = 0; c < 64; c++) s2[c] = __ldg(bsc2 + c);
    for (int k = 0; k < 64; k++) {
        float h = sm[k*128 + tid];
        fma_row(s2, g_Wsc2T + k*64, h);
    }
#pragma unroll
    for (int c = 0; c < 64; c++) sm[c*128 + tid] = fmaxf(s2[c], 0.0f);

    float s3[64];
#pragma unroll
    for (int c = 0; c < 64; c++) s3[c] = __ldg(bsc3 + c);
    for (int k = 0; k < 64; k++) {
        float h = sm[k*128 + tid];
        fma_row(s3, g_Wsc3T + k*64, h);
    }
#pragma unroll
    for (int c = 0; c < 64; c++) g_sc[base + (size_t)c * NN] = fmaxf(s3[c], 0.0f);
}

// ---------------- kernel 5: FlowHead -----------------------------------------
__global__ void __launch_bounds__(128) k_head(
    float* __restrict__ out, const float* __restrict__ bfh1,
    const float* __restrict__ bo1, const float* __restrict__ wo2,
    const float* __restrict__ bo2) {
    __shared__ float sm[64 * 128];
    int tid = threadIdx.x;
    int p = blockIdx.x * 128 + tid;
    int b = p >> 15, n = p & (NN - 1);
    size_t base = (size_t)b * COLSZ + n;
    const float* nn = out;   // net_new lives in d_out already

    float o1[64];
#pragma unroll
    for (int c = 0; c < 64; c++) o1[c] = __ldg(bfh1 + c);
    for (int k = 0; k < 64; k++) {
        float h = __ldg(nn + base + (size_t)k * NN);
        fma_row(o1, g_Wfh1T + k*64, h);
    }
#pragma unroll
    for (int c = 0; c < 64; c++) sm[c*128 + tid] = o1[c];   // NOTE: no relu on o1

    float o[64];
#pragma unroll
    for (int c = 0; c < 64; c++) o[c] = __ldg(bo1 + c);
    for (int k = 0; k < 64; k++) {                         // sc part (cols 0..63)
        float h = g_sc[base + (size_t)k * NN];
        fma_row(o, g_Wo1T + k*64, h);
    }
    for (int k = 0; k < 64; k++) {                         // o1 part (cols 64..127)
        float h = sm[k*128 + tid];
        fma_row(o, g_Wo1T + (64 + k)*64, h);
    }
#pragma unroll
    for (int c = 0; c < 64; c++) o[c] = fmaxf(o[c], 0.0f);

    float d0 = __ldg(bo2 + 0), d1 = __ldg(bo2 + 1), d2 = __ldg(bo2 + 2);
#pragma unroll
    for (int c = 0; c < 64; c++) {
        d0 += __ldg(wo2 +       c) * o[c];
        d1 += __ldg(wo2 +  64 + c) * o[c];
        d2 += __ldg(wo2 + 128 + c) * o[c];
    }
    float* dd = out + (size_t)CH * PP + (size_t)p * 3;     // output #2: delta (B,N,3)
    dd[0] = d0; dd[1] = d1; dd[2] = d2;
}

// ---------------- launch -----------------------------------------------------
extern "C" void kernel_launch(void* const* d_in, const int* in_sizes, int n_in,
                              void* d_out, int out_size) {
    const float* net   = (const float*)d_in[0];
    const float* inp   = (const float*)d_in[1];
    const float* corr  = (const float*)d_in[2];
    const float* flow  = (const float*)d_in[3];
    const int*   edges = (const int*)  d_in[4];
    const float* efeat = (const float*)d_in[5];
    const float* w_corr = (const float*)d_in[6];
    const float* b_corr = (const float*)d_in[7];
    const float* w_flow = (const float*)d_in[8];
    const float* b_flow = (const float*)d_in[9];
    const float* w_me   = (const float*)d_in[10];
    const float* b_me   = (const float*)d_in[11];
    const float* wz = (const float*)d_in[12];
    const float* bz = (const float*)d_in[13];
    const float* wr = (const float*)d_in[14];
    const float* br = (const float*)d_in[15];
    const float* wq = (const float*)d_in[16];
    const float* bq = (const float*)d_in[17];
    const float* w_fh1 = (const float*)d_in[18];
    const float* b_fh1 = (const float*)d_in[19];
    const float* w_sc1 = (const float*)d_in[20];
    const float* b_sc1 = (const float*)d_in[21];
    const float* w_sc2 = (const float*)d_in[22];
    const float* b_sc2 = (const float*)d_in[23];
    const float* w_sc3 = (const float*)d_in[24];
    const float* b_sc3 = (const float*)d_in[25];
    const float* w_out1 = (const float*)d_in[26];
    const float* b_out1 = (const float*)d_in[27];
    const float* w_out2 = (const float*)d_in[28];
    const float* b_out2 = (const float*)d_in[29];
    float* out = (float*)d_out;

    const int blocks = PP / 128;   // 512

    k_prep<<<48, 256>>>(w_corr, w_me, wz, wr, wq, w_fh1, w_sc1, w_sc2, w_sc3, w_out1);
    k_motion<<<blocks, 128>>>(corr, flow, b_corr, b_me, w_flow, b_flow);
    k_zr<<<blocks, 128>>>(net, inp, bz, br);
    k_q<<<blocks, 128>>>(net, inp, bq, out);
    k_setconv<<<blocks, 128>>>(edges, efeat, b_sc1, b_sc2, b_sc3);
    k_head<<<blocks, 128>>>(out, b_fh1, b_out1, w_out2, b_out2);
}